// round 5
// baseline (speedup 1.0000x reference)
#include <cuda_runtime.h>

typedef unsigned long long u64;

#define NQ    12
#define DEPTH 4
#define NPAR  144
#define THREADS 256
#define DYN_SMEM (4 * 4096 * 4)   // exR0, exI0, exR1, exI1 (floats)

// ---------- f32x2 packed helpers ----------
__device__ __forceinline__ u64 f2fma(u64 a, u64 b, u64 c) {
    u64 d; asm("fma.rn.f32x2 %0,%1,%2,%3;" : "=l"(d) : "l"(a), "l"(b), "l"(c)); return d;
}
__device__ __forceinline__ u64 f2mul(u64 a, u64 b) {
    u64 d; asm("mul.rn.f32x2 %0,%1,%2;" : "=l"(d) : "l"(a), "l"(b)); return d;
}
__device__ __forceinline__ u64 pk(float lo, float hi) {
    u64 r; asm("mov.b64 %0,{%1,%2};" : "=l"(r) : "f"(lo), "f"(hi)); return r;
}
__device__ __forceinline__ void upk(u64 v, float& lo, float& hi) {
    asm("mov.b64 {%0,%1},%2;" : "=f"(lo), "=f"(hi) : "l"(v));
}
__device__ __forceinline__ u64 f2swap(u64 v) {
    float lo, hi; upk(v, lo, hi); return pk(hi, lo);
}

struct c2 { float r, i; };
__device__ __forceinline__ c2 cmul(c2 a, c2 b) {
    c2 o; o.r = a.r * b.r - a.i * b.i; o.i = a.r * b.i + a.i * b.r; return o;
}

// ---------- CNOT-ring permutation (matches reference gate order) ----------
__device__ __forceinline__ int perm12(int s) {
    int d = s;
    #pragma unroll
    for (int q = 0; q < 12; q++) {
        int bc = 11 - q, bt = 11 - ((q + 1) % 12);
        d ^= ((d >> bc) & 1) << bt;
    }
    return d;
}
// byte offset of amp d in the exchange arrays (GF2-linear in d's bits)
__device__ __forceinline__ int laddr(int d) {
    return ((d >> 5) << 7) | ((((d >> 1) & 15) ^ ((d >> 5) & 15)) << 3) | ((d & 1) << 2);
}
// byte-offset delta contributed by m (= i[11:8]) in layout-B addressing
__device__ __forceinline__ int bmoff(int m) {
    return (m << 10) | ((m & 1) << 6);
}

#define LOADC(gi)                                                     \
    const u64* rec = gpk + (gi) * 12;                                 \
    ulonglong2 q01 = *(const ulonglong2*)(rec);                       \
    ulonglong2 q23 = *(const ulonglong2*)(rec + 2);                   \
    ulonglong2 q45 = *(const ulonglong2*)(rec + 4);                   \
    u64 PX = q01.x, PY = q01.y, NY = q23.x, PZ = q23.y;               \
    u64 NZ = q45.x, PW = q45.y, NW = rec[6];

// swap-form (pack-lane) gate applied to all 8 packed amps
#define PACK_GATE(gi)                                                 \
    {                                                                 \
        const u64* rec = gpk + (gi) * 12;                             \
        u64 PX = rec[0], PWv = rec[5], NWv = rec[6];                  \
        ulonglong2 mm = *(const ulonglong2*)(rec + 8);                \
        u64 MY = mm.x, MYr = mm.y, MZ = rec[10];                      \
        _Pragma("unroll")                                             \
        for (int p = 0; p < 8; p++) {                                 \
            u64 R = Re[p], I = Im[p];                                 \
            u64 Rs = f2swap(R), Is = f2swap(I);                       \
            Re[p] = f2fma(NWv, Is, f2fma(MZ, Rs, f2fma(MY,  I, f2mul(PX, R)))); \
            Im[p] = f2fma(PWv, Rs, f2fma(MZ, Is, f2fma(MYr, R, f2mul(PX, I)))); \
        }                                                             \
    }

__global__ __launch_bounds__(THREADS, 2)
void qgen_kernel(const float* __restrict__ noise,
                 const float* __restrict__ W1, const float* __restrict__ b1,
                 const float* __restrict__ W2, const float* __restrict__ b2,
                 const float* __restrict__ W3, const float* __restrict__ b3,
                 const float* __restrict__ W4, const float* __restrict__ b4,
                 float* __restrict__ out)
{
    extern __shared__ __align__(16) float dyn[];
    float* exR0 = dyn;              // transpose buffer
    float* exI0 = dyn + 4096;
    float* exR1 = dyn + 8192;       // perm buffer
    float* exI1 = dyn + 12288;

    __shared__ __align__(16) u64   gpk[48 * 12];
    __shared__ float2 s_v[12][2];
    __shared__ float s_nz[12];
    __shared__ float s_h[64];
    __shared__ float s_par[NPAR];
    __shared__ float s_meas[12];
    __shared__ float s_wsum[8][12];
    __shared__ float s_h2[64];

    const int t   = threadIdx.x;
    const int bId = blockIdx.x;

    if (t < 12) s_nz[t] = noise[bId * 12 + t];
    __syncthreads();

    // ---- MLP1 ----
    if (t < 64) {
        float acc = b1[t];
        #pragma unroll
        for (int m = 0; m < 12; m++) acc += s_nz[m] * W1[m * 64 + t];
        s_h[t] = tanhf(acc);
    }
    __syncthreads();

    // ---- MLP2 ----
    if (t < NPAR) {
        float acc = b2[t];
        #pragma unroll 8
        for (int j = 0; j < 64; j++) acc += s_h[j] * W2[j * NPAR + t];
        s_par[t] = acc;
    }
    __syncthreads();

    // ---- per-gate SU(2): U = RZ(c)RY(b)RX(a) = [[gx+igy, gz+igw],[-(gz-igw), gx-igy]]
    if (t < 48) {
        float a = s_par[t * 3 + 0], b = s_par[t * 3 + 1], c = s_par[t * 3 + 2];
        float ca, sa, cb, sb, cc, sc;
        sincosf(0.5f * a, &sa, &ca);
        sincosf(0.5f * b, &sb, &cb);
        sincosf(0.5f * c, &sc, &cc);
        float x = cb * ca, y = sb * sa, z = sb * ca, w = cb * sa;
        float gx =  cc * x + sc * y;
        float gy =  cc * y - sc * x;
        float gz = -(cc * z + sc * w);
        float gw =  sc * z - cc * w;
        u64* r = gpk + t * 12;
        r[0]  = pk(gx, gx);  r[1] = pk(gy, gy);  r[2] = pk(-gy, -gy);
        r[3]  = pk(gz, gz);  r[4] = pk(-gz, -gz);
        r[5]  = pk(gw, gw);  r[6] = pk(-gw, -gw);
        r[8]  = pk(-gy, gy); r[9] = pk(gy, -gy); r[10] = pk(gz, -gz);
        if (t < 12) {   // layer-0 gate: U|0> = (gx+igy, -(gz-igw))
            s_v[t][0] = make_float2(gx, gy);
            s_v[t][1] = make_float2(-gz, gw);
        }
    }

    // ---- per-thread exchange addresses ----
    // Layout A: thread t = i[11:4], regs = i[3:0] = (p<<1)|lane (pack = i0)
    const int AbU = ((t >> 1) << 4) | (((t & 1) << 3) ^ ((t >> 1) & 15));
    // Layout B: thread u=t = i[7:0], regs m = i[11:8] = (pB<<1)|laneB (pack = i8)
    const int uh  = t >> 5;
    const int Bb  = (uh << 7) | ((((t >> 1) & 15) ^ uh) << 3) | ((t & 1) << 2);
    const int puA = laddr(perm12(t));

    u64* exR0_64 = (u64*)exR0;
    u64* exI0_64 = (u64*)exI0;
    u64* exR1_64 = (u64*)exR1;
    u64* exI1_64 = (u64*)exI1;

    __syncthreads();   // gpk + s_v visible

    // ---- layer 0 (gates + CNOT ring) via product-state synthesis ----
    u64 Re[8], Im[8];
    {
        c2 v[12][2];
        #pragma unroll
        for (int q = 0; q < 12; q++) {
            float2 a0 = s_v[q][0], a1 = s_v[q][1];
            v[q][0].r = a0.x; v[q][0].i = a0.y;
            v[q][1].r = a1.x; v[q][1].i = a1.y;
        }
        const int x2 = ((t >> 5) ^ (t >> 6)) & 1;
        const int x3 = ((t >> 4) ^ (t >> 5)) & 1;
        const int x4 = ((t >> 3) ^ (t >> 4)) & 1;
        const int x5 = ((t >> 2) ^ (t >> 3)) & 1;
        const int x6 = ((t >> 1) ^ (t >> 2)) & 1;
        const int x7 = ( t       ^ (t >> 1)) & 1;
        const int e0 = (t >> 7) & 1;                 // i11
        const int e1 = ((t >> 6) ^ (t >> 7)) & 1;    // i10^i11
        const int e4 = t & 1;                        // i4

        c2 base = cmul(cmul(cmul(v[2][x2], v[3][x3]), cmul(v[4][x4], v[5][x5])),
                       cmul(v[6][x6], v[7][x7]));
        c2 base2[2];
        base2[0] = cmul(base, v[8][e4]);
        base2[1] = cmul(base, v[8][e4 ^ 1]);

        c2 A[2];
        A[0] = cmul(v[0][e0],     v[1][e1]);
        A[1] = cmul(v[0][e0 ^ 1], v[1][e1 ^ 1]);
        c2 B[4];
        B[0] = cmul(A[0], v[11][0]);
        B[1] = cmul(A[1], v[11][1]);
        B[2] = cmul(A[0], v[11][1]);
        B[3] = cmul(A[1], v[11][0]);
        c2 C[8];
        #pragma unroll
        for (int k2 = 0; k2 < 2; k2++)
            #pragma unroll
            for (int j = 0; j < 4; j++)
                C[k2 * 4 + j] = cmul(B[j], v[10][((j >> 1) & 1) ^ k2]);
        #pragma unroll
        for (int k3 = 0; k3 < 2; k3++)
            #pragma unroll
            for (int j = 0; j < 8; j += 2) {
                c2 d0 = cmul(cmul(C[j],     v[9][((j >> 2) & 1) ^ k3]), base2[k3]);
                c2 d1 = cmul(cmul(C[j + 1], v[9][(((j+1) >> 2) & 1) ^ k3]), base2[k3]);
                int p = (k3 * 8 + j) >> 1;
                Re[p] = pk(d0.r, d1.r);
                Im[p] = pk(d0.i, d1.i);
            }
    }

    // ---- layers 1..3 ----
    #pragma unroll 1
    for (int l = 1; l < DEPTH; l++) {
        // q=11 : pack-lane gate in layout A
        PACK_GATE(l * 12 + 11)
        // q=10,9,8 : register-pair lanewise gates
        #pragma unroll
        for (int qq = 0; qq < 3; qq++) {
            const int gi = l * 12 + 10 - qq;
            const int mask = 1 << qq;
            LOADC(gi)
            #pragma unroll
            for (int p0 = 0; p0 < 8; p0++) {
                if (p0 & mask) continue;
                const int p1 = p0 | mask;
                u64 aR = Re[p0], aI = Im[p0], bR = Re[p1], bI = Im[p1];
                Re[p0] = f2fma(NW, bI, f2fma(PZ, bR, f2fma(NY, aI, f2mul(PX, aR))));
                Im[p0] = f2fma(PW, bR, f2fma(PZ, bI, f2fma(PY, aR, f2mul(PX, aI))));
                Re[p1] = f2fma(NW, aI, f2fma(NZ, aR, f2fma(PY, bI, f2mul(PX, bR))));
                Im[p1] = f2fma(PW, aR, f2fma(NZ, aI, f2fma(NY, bR, f2mul(PX, bI))));
            }
        }
        // q=7..4 : lane-shuffle gates (q=3 moved to layout B pack gate)
        #pragma unroll
        for (int tb = 0; tb < 4; tb++) {
            const int gi = l * 12 + 7 - tb;
            const int lm = 1 << tb;
            LOADC(gi)
            const int mybit = (t >> tb) & 1;
            u64 Ya = mybit ? PY : NY;
            u64 Yb = mybit ? NY : PY;
            u64 Zc = mybit ? NZ : PZ;
            #pragma unroll
            for (int p = 0; p < 8; p++) {
                u64 mR = Re[p], mI = Im[p];
                u64 oR = __shfl_xor_sync(0xffffffffu, mR, lm);
                u64 oI = __shfl_xor_sync(0xffffffffu, mI, lm);
                Re[p] = f2fma(NW, oI, f2fma(Zc, oR, f2fma(Ya, mI, f2mul(PX, mR))));
                Im[p] = f2fma(PW, oR, f2fma(Zc, oI, f2fma(Yb, mR, f2mul(PX, mI))));
            }
        }

        // transpose A -> B (buffer 0, single barrier: buffer alternation
        // guarantees prior reads of buf0 drained at the previous perm barrier)
        #pragma unroll
        for (int p = 0; p < 8; p++) {
            exR0_64[AbU ^ p] = Re[p];
            exI0_64[AbU ^ p] = Im[p];
        }
        __syncthreads();
        #pragma unroll
        for (int pB = 0; pB < 8; pB++) {
            const int a0 = Bb ^ bmoff(2 * pB);
            const int a1 = Bb ^ bmoff(2 * pB + 1);
            float r0 = *(const float*)((const char*)exR0 + a0);
            float r1 = *(const float*)((const char*)exR0 + a1);
            float i0 = *(const float*)((const char*)exI0 + a0);
            float i1 = *(const float*)((const char*)exI0 + a1);
            Re[pB] = pk(r0, r1);
            Im[pB] = pk(i0, i1);
        }

        // q=3 : pack-lane gate in layout B (pack bit = i8 = qubit 3)
        PACK_GATE(l * 12 + 3)
        // q=2,1,0 : lanewise in layout B
        #pragma unroll
        for (int qq = 0; qq < 3; qq++) {
            const int gi = l * 12 + 2 - qq;
            const int mask = 1 << qq;
            LOADC(gi)
            #pragma unroll
            for (int p0 = 0; p0 < 8; p0++) {
                if (p0 & mask) continue;
                const int p1 = p0 | mask;
                u64 aR = Re[p0], aI = Im[p0], bR = Re[p1], bI = Im[p1];
                Re[p0] = f2fma(NW, bI, f2fma(PZ, bR, f2fma(NY, aI, f2mul(PX, aR))));
                Im[p0] = f2fma(PW, bR, f2fma(PZ, bI, f2fma(PY, aR, f2mul(PX, aI))));
                Re[p1] = f2fma(NW, aI, f2fma(NZ, aR, f2fma(PY, bI, f2mul(PX, bR))));
                Im[p1] = f2fma(PW, aR, f2fma(NZ, aI, f2fma(NY, bR, f2mul(PX, bI))));
            }
        }

        if (l == DEPTH - 1) break;   // last ring folded into measurement signs

        // CNOT-ring permutation scatter, back to layout A (buffer 1)
        #pragma unroll
        for (int pB = 0; pB < 8; pB++) {
            float r0, r1, i0v, i1v;
            upk(Re[pB], r0, r1);
            upk(Im[pB], i0v, i1v);
            const int a0 = puA ^ laddr(perm12((2 * pB) << 8));
            const int a1 = puA ^ laddr(perm12((2 * pB + 1) << 8));
            *(float*)((char*)exR1 + a0) = r0;  *(float*)((char*)exI1 + a0) = i0v;
            *(float*)((char*)exR1 + a1) = r1;  *(float*)((char*)exI1 + a1) = i1v;
        }
        __syncthreads();
        #pragma unroll
        for (int p = 0; p < 8; p++) {
            Re[p] = exR1_64[AbU ^ p];
            Im[p] = exI1_64[AbU ^ p];
        }
    }

    // ---- <Z_q> in layout B with post-ring prefix-parity signs ----
    float T0 = 0.f, T1 = 0.f, T2 = 0.f, T3 = 0.f;
    #pragma unroll
    for (int pB = 0; pB < 8; pB++) {
        u64 p2 = f2fma(Im[pB], Im[pB], f2mul(Re[pB], Re[pB]));
        float pl, ph; upk(p2, pl, ph);
        float sm = pl + ph, df = pl - ph;
        T0 += (__popc(pB & 3) & 1) ? -df : df;
        T1 += (__popc(pB & 6) & 1) ? -sm : sm;
        T2 += (__popc(pB & 7) & 1) ? -sm : sm;
        T3 += (__popc(pB & 7) & 1) ? -df : df;
    }
    float c[12];
    c[0] = (__popc(t) & 1) ? -T0 : T0;
    c[1] = T1; c[2] = T2; c[3] = T3;
    #pragma unroll
    for (int q = 4; q < 12; q++) {
        const int tmask = (0xFF << (11 - q)) & 0xFF;
        c[q] = (__popc(t & tmask) & 1) ? -T3 : T3;
    }

    #pragma unroll
    for (int s = 16; s >= 1; s >>= 1) {
        #pragma unroll
        for (int q = 0; q < 12; q++)
            c[q] += __shfl_xor_sync(0xffffffffu, c[q], s);
    }
    const int warp = t >> 5, lane = t & 31;
    if (lane == 0) {
        #pragma unroll
        for (int q = 0; q < 12; q++) s_wsum[warp][q] = c[q];
    }
    __syncthreads();
    if (t < 12) {
        float m = 0.f;
        #pragma unroll
        for (int w = 0; w < 8; w++) m += s_wsum[w][t];
        s_meas[t] = m;
    }
    __syncthreads();

    // ---- MLP3 ----
    if (t < 64) {
        float acc = b3[t];
        #pragma unroll
        for (int q = 0; q < 12; q++) acc += s_meas[q] * W3[q * 64 + t];
        s_h2[t] = tanhf(acc);
    }
    __syncthreads();

    // ---- out ----
    if (t < 2) {
        float acc = b4[t];
        #pragma unroll 8
        for (int j = 0; j < 64; j++) acc += s_h2[j] * W4[j * 2 + t];
        out[bId * 2 + t] = acc;
    }
}

extern "C" void kernel_launch(void* const* d_in, const int* in_sizes, int n_in,
                              void* d_out, int out_size)
{
    (void)n_in; (void)out_size;
    const float* noise = (const float*)d_in[0];
    const float* W1    = (const float*)d_in[1];
    const float* b1    = (const float*)d_in[2];
    const float* W2    = (const float*)d_in[3];
    const float* b2    = (const float*)d_in[4];
    const float* W3    = (const float*)d_in[5];
    const float* b3    = (const float*)d_in[6];
    const float* W4    = (const float*)d_in[7];
    const float* b4    = (const float*)d_in[8];
    float* out = (float*)d_out;

    cudaFuncSetAttribute(qgen_kernel,
                         cudaFuncAttributeMaxDynamicSharedMemorySize, DYN_SMEM);

    const int B = in_sizes[0] / NQ;
    qgen_kernel<<<B, THREADS, DYN_SMEM>>>(noise, W1, b1, W2, b2, W3, b3, W4, b4, out);
}

// round 6
// speedup vs baseline: 1.0490x; 1.0490x over previous
#include <cuda_runtime.h>

typedef unsigned long long u64;

#define NQ    12
#define DEPTH 4
#define NPAR  144
#define THREADS 256

// ---------- f32x2 packed helpers ----------
__device__ __forceinline__ u64 f2fma(u64 a, u64 b, u64 c) {
    u64 d; asm("fma.rn.f32x2 %0,%1,%2,%3;" : "=l"(d) : "l"(a), "l"(b), "l"(c)); return d;
}
__device__ __forceinline__ u64 f2mul(u64 a, u64 b) {
    u64 d; asm("mul.rn.f32x2 %0,%1,%2;" : "=l"(d) : "l"(a), "l"(b)); return d;
}
__device__ __forceinline__ u64 pk(float lo, float hi) {
    u64 r; asm("mov.b64 %0,{%1,%2};" : "=l"(r) : "f"(lo), "f"(hi)); return r;
}
__device__ __forceinline__ void upk(u64 v, float& lo, float& hi) {
    asm("mov.b64 {%0,%1},%2;" : "=f"(lo), "=f"(hi) : "l"(v));
}
__device__ __forceinline__ u64 f2swap(u64 v) {
    float lo, hi; upk(v, lo, hi); return pk(hi, lo);
}

struct c2 { float r, i; };
__device__ __forceinline__ c2 cmul(c2 a, c2 b) {
    c2 o; o.r = a.r * b.r - a.i * b.i; o.i = a.r * b.i + a.i * b.r; return o;
}

// ---------- CNOT-ring permutation (matches reference gate order) ----------
__device__ __forceinline__ int perm12(int s) {
    int d = s;
    #pragma unroll
    for (int q = 0; q < 12; q++) {
        int bc = 11 - q, bt = 11 - ((q + 1) % 12);
        d ^= ((d >> bc) & 1) << bt;
    }
    return d;
}
// byte offset of amp d in the exchange arrays (GF2-linear in d's bits)
__device__ __forceinline__ int laddr(int d) {
    return ((d >> 5) << 7) | ((((d >> 1) & 15) ^ ((d >> 5) & 15)) << 3) | ((d & 1) << 2);
}
// byte-offset delta contributed by m (= i[11:8]) in layout-B addressing
__device__ __forceinline__ int bmoff(int m) {
    return (m << 10) | ((m & 1) << 6);
}

#define LOADC(gi)                                                     \
    const u64* rec = gpk + (gi) * 12;                                 \
    ulonglong2 q01 = *(const ulonglong2*)(rec);                       \
    ulonglong2 q23 = *(const ulonglong2*)(rec + 2);                   \
    ulonglong2 q45 = *(const ulonglong2*)(rec + 4);                   \
    u64 PX = q01.x, PY = q01.y, NY = q23.x, PZ = q23.y;               \
    u64 NZ = q45.x, PW = q45.y, NW = rec[6];

// swap-form (pack-lane) gate applied to all 8 packed amps
#define PACK_GATE(gi)                                                 \
    {                                                                 \
        const u64* rec = gpk + (gi) * 12;                             \
        u64 PX = rec[0], PWv = rec[5], NWv = rec[6];                  \
        ulonglong2 mm = *(const ulonglong2*)(rec + 8);                \
        u64 MY = mm.x, MYr = mm.y, MZ = rec[10];                      \
        _Pragma("unroll")                                             \
        for (int p = 0; p < 8; p++) {                                 \
            u64 R = Re[p], I = Im[p];                                 \
            u64 Rs = f2swap(R), Is = f2swap(I);                       \
            Re[p] = f2fma(NWv, Is, f2fma(MZ, Rs, f2fma(MY,  I, f2mul(PX, R)))); \
            Im[p] = f2fma(PWv, Rs, f2fma(MZ, Is, f2fma(MYr, R, f2mul(PX, I)))); \
        }                                                             \
    }

__global__ __launch_bounds__(THREADS, 2)
void qgen_kernel(const float* __restrict__ noise,
                 const float* __restrict__ W1, const float* __restrict__ b1,
                 const float* __restrict__ W2, const float* __restrict__ b2,
                 const float* __restrict__ W3, const float* __restrict__ b3,
                 const float* __restrict__ W4, const float* __restrict__ b4,
                 float* __restrict__ out)
{
    __shared__ __align__(16) float exR[4096];
    __shared__ __align__(16) float exI[4096];
    __shared__ __align__(16) u64   gpk[48 * 12];
    __shared__ float2 s_v[12][2];
    __shared__ float s_nz[12];
    __shared__ float s_h[64];
    __shared__ float s_par[NPAR];
    __shared__ float s_meas[12];
    __shared__ float s_wsum[8][12];
    __shared__ float s_h2[64];

    const int t   = threadIdx.x;
    const int bId = blockIdx.x;

    if (t < 12) s_nz[t] = noise[bId * 12 + t];
    __syncthreads();

    // ---- MLP1 ----
    if (t < 64) {
        float acc = b1[t];
        #pragma unroll
        for (int m = 0; m < 12; m++) acc += s_nz[m] * W1[m * 64 + t];
        s_h[t] = tanhf(acc);
    }
    __syncthreads();

    // ---- MLP2 ----
    if (t < NPAR) {
        float acc = b2[t];
        #pragma unroll 8
        for (int j = 0; j < 64; j++) acc += s_h[j] * W2[j * NPAR + t];
        s_par[t] = acc;
    }
    __syncthreads();

    // ---- per-gate SU(2): U = RZ(c)RY(b)RX(a) = [[gx+igy, gz+igw],[-(gz-igw), gx-igy]]
    if (t < 48) {
        float a = s_par[t * 3 + 0], b = s_par[t * 3 + 1], c = s_par[t * 3 + 2];
        float ca, sa, cb, sb, cc, sc;
        sincosf(0.5f * a, &sa, &ca);
        sincosf(0.5f * b, &sb, &cb);
        sincosf(0.5f * c, &sc, &cc);
        float x = cb * ca, y = sb * sa, z = sb * ca, w = cb * sa;
        float gx =  cc * x + sc * y;
        float gy =  cc * y - sc * x;
        float gz = -(cc * z + sc * w);
        float gw =  sc * z - cc * w;
        u64* r = gpk + t * 12;
        r[0]  = pk(gx, gx);  r[1] = pk(gy, gy);  r[2] = pk(-gy, -gy);
        r[3]  = pk(gz, gz);  r[4] = pk(-gz, -gz);
        r[5]  = pk(gw, gw);  r[6] = pk(-gw, -gw);
        r[8]  = pk(-gy, gy); r[9] = pk(gy, -gy); r[10] = pk(gz, -gz);
        if (t < 12) {   // layer-0 gate: U|0> = (gx+igy, -(gz-igw))
            s_v[t][0] = make_float2(gx, gy);
            s_v[t][1] = make_float2(-gz, gw);
        }
    }

    // ---- per-thread exchange addresses ----
    // Layout A: thread t = i[11:4], regs = i[3:0] = (p<<1)|lane (pack = i0)
    const int AbU = ((t >> 1) << 4) | (((t & 1) << 3) ^ ((t >> 1) & 15));
    // Layout B: thread u=t = i[7:0], regs m = i[11:8] = (pB<<1)|laneB (pack = i8)
    const int uh  = t >> 5;
    const int Bb  = (uh << 7) | ((((t >> 1) & 15) ^ uh) << 3) | ((t & 1) << 2);
    const int puA = laddr(perm12(t));

    u64* exR64 = (u64*)exR;
    u64* exI64 = (u64*)exI;

    __syncthreads();   // gpk + s_v visible

    // ---- layer 0 (gates + CNOT ring) via product-state synthesis ----
    u64 Re[8], Im[8];
    {
        c2 v[12][2];
        #pragma unroll
        for (int q = 0; q < 12; q++) {
            float2 a0 = s_v[q][0], a1 = s_v[q][1];
            v[q][0].r = a0.x; v[q][0].i = a0.y;
            v[q][1].r = a1.x; v[q][1].i = a1.y;
        }
        const int x2 = ((t >> 5) ^ (t >> 6)) & 1;
        const int x3 = ((t >> 4) ^ (t >> 5)) & 1;
        const int x4 = ((t >> 3) ^ (t >> 4)) & 1;
        const int x5 = ((t >> 2) ^ (t >> 3)) & 1;
        const int x6 = ((t >> 1) ^ (t >> 2)) & 1;
        const int x7 = ( t       ^ (t >> 1)) & 1;
        const int e0 = (t >> 7) & 1;                 // i11
        const int e1 = ((t >> 6) ^ (t >> 7)) & 1;    // i10^i11
        const int e4 = t & 1;                        // i4

        c2 base = cmul(cmul(cmul(v[2][x2], v[3][x3]), cmul(v[4][x4], v[5][x5])),
                       cmul(v[6][x6], v[7][x7]));
        c2 base2[2];
        base2[0] = cmul(base, v[8][e4]);
        base2[1] = cmul(base, v[8][e4 ^ 1]);

        c2 A[2];
        A[0] = cmul(v[0][e0],     v[1][e1]);
        A[1] = cmul(v[0][e0 ^ 1], v[1][e1 ^ 1]);
        c2 B[4];
        B[0] = cmul(A[0], v[11][0]);
        B[1] = cmul(A[1], v[11][1]);
        B[2] = cmul(A[0], v[11][1]);
        B[3] = cmul(A[1], v[11][0]);
        c2 C[8];
        #pragma unroll
        for (int k2 = 0; k2 < 2; k2++)
            #pragma unroll
            for (int j = 0; j < 4; j++)
                C[k2 * 4 + j] = cmul(B[j], v[10][((j >> 1) & 1) ^ k2]);
        #pragma unroll
        for (int k3 = 0; k3 < 2; k3++)
            #pragma unroll
            for (int j = 0; j < 8; j += 2) {
                c2 d0 = cmul(cmul(C[j],     v[9][((j >> 2) & 1) ^ k3]), base2[k3]);
                c2 d1 = cmul(cmul(C[j + 1], v[9][(((j+1) >> 2) & 1) ^ k3]), base2[k3]);
                int p = (k3 * 8 + j) >> 1;
                Re[p] = pk(d0.r, d1.r);
                Im[p] = pk(d0.i, d1.i);
            }
    }

    // ---- layers 1..3 ----
    #pragma unroll 1
    for (int l = 1; l < DEPTH; l++) {
        // q=11 : pack-lane gate in layout A
        PACK_GATE(l * 12 + 11)
        // q=10,9,8 : register-pair lanewise gates
        #pragma unroll
        for (int qq = 0; qq < 3; qq++) {
            const int gi = l * 12 + 10 - qq;
            const int mask = 1 << qq;
            LOADC(gi)
            #pragma unroll
            for (int p0 = 0; p0 < 8; p0++) {
                if (p0 & mask) continue;
                const int p1 = p0 | mask;
                u64 aR = Re[p0], aI = Im[p0], bR = Re[p1], bI = Im[p1];
                Re[p0] = f2fma(NW, bI, f2fma(PZ, bR, f2fma(NY, aI, f2mul(PX, aR))));
                Im[p0] = f2fma(PW, bR, f2fma(PZ, bI, f2fma(PY, aR, f2mul(PX, aI))));
                Re[p1] = f2fma(NW, aI, f2fma(NZ, aR, f2fma(PY, bI, f2mul(PX, bR))));
                Im[p1] = f2fma(PW, aR, f2fma(NZ, aI, f2fma(NY, bR, f2mul(PX, bI))));
            }
        }
        // q=7..4 : lane-shuffle gates (q=3 handled as layout-B pack gate)
        #pragma unroll
        for (int tb = 0; tb < 4; tb++) {
            const int gi = l * 12 + 7 - tb;
            const int lm = 1 << tb;
            LOADC(gi)
            const int mybit = (t >> tb) & 1;
            u64 Ya = mybit ? PY : NY;
            u64 Yb = mybit ? NY : PY;
            u64 Zc = mybit ? NZ : PZ;
            #pragma unroll
            for (int p = 0; p < 8; p++) {
                u64 mR = Re[p], mI = Im[p];
                u64 oR = __shfl_xor_sync(0xffffffffu, mR, lm);
                u64 oI = __shfl_xor_sync(0xffffffffu, mI, lm);
                Re[p] = f2fma(NW, oI, f2fma(Zc, oR, f2fma(Ya, mI, f2mul(PX, mR))));
                Im[p] = f2fma(PW, oR, f2fma(Zc, oI, f2fma(Yb, mR, f2mul(PX, mI))));
            }
        }

        // transpose A -> B (static buffer, 2-barrier round trip)
        __syncthreads();
        #pragma unroll
        for (int p = 0; p < 8; p++) {
            exR64[AbU ^ p] = Re[p];
            exI64[AbU ^ p] = Im[p];
        }
        __syncthreads();
        #pragma unroll
        for (int pB = 0; pB < 8; pB++) {
            const int a0 = Bb ^ bmoff(2 * pB);
            const int a1 = Bb ^ bmoff(2 * pB + 1);
            float r0 = *(const float*)((const char*)exR + a0);
            float r1 = *(const float*)((const char*)exR + a1);
            float i0 = *(const float*)((const char*)exI + a0);
            float i1 = *(const float*)((const char*)exI + a1);
            Re[pB] = pk(r0, r1);
            Im[pB] = pk(i0, i1);
        }

        // q=3 : pack-lane gate in layout B (pack bit = i8 = qubit 3)
        PACK_GATE(l * 12 + 3)
        // q=2,1,0 : lanewise in layout B
        #pragma unroll
        for (int qq = 0; qq < 3; qq++) {
            const int gi = l * 12 + 2 - qq;
            const int mask = 1 << qq;
            LOADC(gi)
            #pragma unroll
            for (int p0 = 0; p0 < 8; p0++) {
                if (p0 & mask) continue;
                const int p1 = p0 | mask;
                u64 aR = Re[p0], aI = Im[p0], bR = Re[p1], bI = Im[p1];
                Re[p0] = f2fma(NW, bI, f2fma(PZ, bR, f2fma(NY, aI, f2mul(PX, aR))));
                Im[p0] = f2fma(PW, bR, f2fma(PZ, bI, f2fma(PY, aR, f2mul(PX, aI))));
                Re[p1] = f2fma(NW, aI, f2fma(NZ, aR, f2fma(PY, bI, f2mul(PX, bR))));
                Im[p1] = f2fma(PW, aR, f2fma(NZ, aI, f2fma(NY, bR, f2mul(PX, bI))));
            }
        }

        if (l == DEPTH - 1) break;   // last ring folded into measurement signs

        // CNOT-ring permutation scatter, back to layout A
        __syncthreads();
        #pragma unroll
        for (int pB = 0; pB < 8; pB++) {
            float r0, r1, i0v, i1v;
            upk(Re[pB], r0, r1);
            upk(Im[pB], i0v, i1v);
            const int a0 = puA ^ laddr(perm12((2 * pB) << 8));
            const int a1 = puA ^ laddr(perm12((2 * pB + 1) << 8));
            *(float*)((char*)exR + a0) = r0;  *(float*)((char*)exI + a0) = i0v;
            *(float*)((char*)exR + a1) = r1;  *(float*)((char*)exI + a1) = i1v;
        }
        __syncthreads();
        #pragma unroll
        for (int p = 0; p < 8; p++) {
            Re[p] = exR64[AbU ^ p];
            Im[p] = exI64[AbU ^ p];
        }
    }

    // ---- <Z_q> in layout B with post-ring prefix-parity signs ----
    float T0 = 0.f, T1 = 0.f, T2 = 0.f, T3 = 0.f;
    #pragma unroll
    for (int pB = 0; pB < 8; pB++) {
        u64 p2 = f2fma(Im[pB], Im[pB], f2mul(Re[pB], Re[pB]));
        float pl, ph; upk(p2, pl, ph);
        float sm = pl + ph, df = pl - ph;
        T0 += (__popc(pB & 3) & 1) ? -df : df;
        T1 += (__popc(pB & 6) & 1) ? -sm : sm;
        T2 += (__popc(pB & 7) & 1) ? -sm : sm;
        T3 += (__popc(pB & 7) & 1) ? -df : df;
    }
    float c[12];
    c[0] = (__popc(t) & 1) ? -T0 : T0;
    c[1] = T1; c[2] = T2; c[3] = T3;
    #pragma unroll
    for (int q = 4; q < 12; q++) {
        const int tmask = (0xFF << (11 - q)) & 0xFF;
        c[q] = (__popc(t & tmask) & 1) ? -T3 : T3;
    }

    #pragma unroll
    for (int s = 16; s >= 1; s >>= 1) {
        #pragma unroll
        for (int q = 0; q < 12; q++)
            c[q] += __shfl_xor_sync(0xffffffffu, c[q], s);
    }
    const int warp = t >> 5, lane = t & 31;
    if (lane == 0) {
        #pragma unroll
        for (int q = 0; q < 12; q++) s_wsum[warp][q] = c[q];
    }
    __syncthreads();
    if (t < 12) {
        float m = 0.f;
        #pragma unroll
        for (int w = 0; w < 8; w++) m += s_wsum[w][t];
        s_meas[t] = m;
    }
    __syncthreads();

    // ---- MLP3 ----
    if (t < 64) {
        float acc = b3[t];
        #pragma unroll
        for (int q = 0; q < 12; q++) acc += s_meas[q] * W3[q * 64 + t];
        s_h2[t] = tanhf(acc);
    }
    __syncthreads();

    // ---- out ----
    if (t < 2) {
        float acc = b4[t];
        #pragma unroll 8
        for (int j = 0; j < 64; j++) acc += s_h2[j] * W4[j * 2 + t];
        out[bId * 2 + t] = acc;
    }
}

extern "C" void kernel_launch(void* const* d_in, const int* in_sizes, int n_in,
                              void* d_out, int out_size)
{
    (void)n_in; (void)out_size;
    const float* noise = (const float*)d_in[0];
    const float* W1    = (const float*)d_in[1];
    const float* b1    = (const float*)d_in[2];
    const float* W2    = (const float*)d_in[3];
    const float* b2    = (const float*)d_in[4];
    const float* W3    = (const float*)d_in[5];
    const float* b3    = (const float*)d_in[6];
    const float* W4    = (const float*)d_in[7];
    const float* b4    = (const float*)d_in[8];
    float* out = (float*)d_out;

    const int B = in_sizes[0] / NQ;
    qgen_kernel<<<B, THREADS>>>(noise, W1, b1, W2, b2, W3, b3, W4, b4, out);
}